// round 17
// speedup vs baseline: 2.8228x; 1.0427x over previous
#include <cuda_runtime.h>
#include <cuda_fp16.h>
#include <math.h>
#include <cstdint>

#define N_NODES 50000
#define N_EDGES 400000
#define BATCH 4
#define R (N_NODES*BATCH)      /* 200000 rows (n,b) */
#define RPAD 200064            /* padded to 128-row GEMM tiles */
#define BN_EPS 1e-5f
#define SLOPE 0.01f
#define NB_SCAN ((N_NODES + 255) / 256)   /* 196 */
#define DEG_SCALE 1099511627776.0         /* 2^40 */
#define GR4 ((N_NODES*4 + 255) / 256)     /* 782 blocks, 4 thr/node */

/* ---------------- static device scratch (no allocations allowed) -------- */
__device__ __align__(16) unsigned long long g_deg64[N_NODES]; /* zeroed by tail */
__device__ __align__(16) float g_dis[N_NODES];
__device__ __align__(16) int   g_rowptr[N_NODES+1];
__device__ __align__(16) int   g_cur[N_NODES];
__device__ __align__(16) int2  g_colw[N_EDGES];     /* packed {col, w bits} */
__device__ __align__(16) int   g_bsum[256];
__device__ __align__(16) int   g_flag[256];         /* zeroed by tail kernel */
__device__ __align__(16) int   g_gbar[8];           /* grid barriers, zeroed by tail */

/* fp16 layer-1 features: [row][4 halfs] = [row][2 u32]; node owns 4 rows */
__device__ __align__(16) uint32_t g_x16 [RPAD*2];
__device__ __align__(16) uint32_t g_pa16[RPAD*2];
__device__ __align__(16) uint32_t g_pb16[RPAD*2];
__device__ __align__(16) uint32_t g_pc16[RPAD*2];

/* float scratch for layer-3 p-values ([R][2] each) */
__device__ __align__(16) float g_pa[RPAD*4];
__device__ __align__(16) float g_pb[RPAD*4];
__device__ __align__(16) float g_pc[RPAD*4];
__device__ __align__(16) float g_sa[RPAD*2];
__device__ __align__(16) float g_sb[RPAD*2];

/* fp16 hidden states: [row][64] halfs = [row][32] u32 */
__device__ __align__(16) uint32_t g_h16 [RPAD*32];
__device__ __align__(16) uint32_t g_t116[RPAD*32];
__device__ __align__(16) uint32_t g_t216[RPAD*32];
__device__ __align__(16) uint32_t g_t316[RPAD*32];

/* W2 transposed [64 n][128 kpair], fp16x2-packed */
__device__ __align__(16) uint32_t g_w2p_hi[64*128];
/* W1 transposed [64 n][8 kpair], fp16x2-packed hi/lo (K=16) */
__device__ __align__(16) uint32_t g_w1p_hi[64*8];
__device__ __align__(16) uint32_t g_w1p_lo[64*8];

#define MMAH(C, a0,a1,a2,a3, b0,b1) \
    asm volatile("mma.sync.aligned.m16n8k16.row.col.f32.f16.f16.f32 " \
        "{%0,%1,%2,%3},{%4,%5,%6,%7},{%8,%9},{%0,%1,%2,%3};" \
        : "+f"((C)[0]),"+f"((C)[1]),"+f"((C)[2]),"+f"((C)[3]) \
        : "r"(a0),"r"(a1),"r"(a2),"r"(a3),"r"(b0),"r"(b1))

__device__ __forceinline__ uint32_t h2u(__half2 h) {
    uint32_t u; memcpy(&u, &h, 4); return u;
}
__device__ __forceinline__ __half2 u2h(uint32_t u) {
    __half2 h; memcpy(&h, &u, 4); return h;
}

/* grid barrier: all blocks co-resident (guaranteed by launch bounds) */
__device__ __forceinline__ void gridbar(int* cnt, int ngrid) {
    __syncthreads();
    __threadfence();
    if (threadIdx.x == 0) {
        atomicAdd(cnt, 1);
        while (atomicAdd(cnt, 0) < ngrid) { }
    }
    __syncthreads();
}

/* ---------------- preprocessing --------------------------------------- */
__global__ void k_deg_w2(const int* __restrict__ dst, const float* __restrict__ ew,
                         const float* __restrict__ x,
                         const float* __restrict__ W2, const float* __restrict__ W1) {
    int e = blockIdx.x*blockDim.x + threadIdx.x;
    if (e < N_EDGES) {
        int d = dst[e];
        unsigned long long pk =
            (1ULL << 52) |
            (unsigned long long)__double2ll_rn((double)ew[e] * DEG_SCALE);
        atomicAdd(&g_deg64[d], pk);
    }
    if (e < R) {
        int b = e / N_NODES, n = e - b*N_NODES;
        float4 v = ((const float4*)x)[e];
        uint2 pk;
        pk.x = h2u(__floats2half2_rn(v.x, v.y));
        pk.y = h2u(__floats2half2_rn(v.z, v.w));
        *(uint2*)&g_x16[(size_t)(n*4 + b)*2] = pk;
    }
    if (e < 64*128) {
        int n = e >> 7, p = e & 127;
        int k0 = 2*p;
        int sel = k0 >> 6, kk = k0 & 63;
        float v0 = W2[sel*4096 + kk*64 + n];
        float v1 = W2[sel*4096 + (kk+1)*64 + n];
        g_w2p_hi[e] = h2u(__floats2half2_rn(v0, v1));
    }
    if (e < 64*8) {
        int n = e >> 3, p = e & 7;
        int k0 = 2*p;
        float v0 = W1[k0*64 + n];
        float v1 = W1[(k0+1)*64 + n];
        __half h0 = __float2half_rn(v0), h1 = __float2half_rn(v1);
        float l0 = v0 - __half2float(h0), l1 = v1 - __half2float(h1);
        g_w1p_hi[e] = h2u(__halves2half2(h0, h1));
        g_w1p_lo[e] = h2u(__floats2half2_rn(l0, l1));
    }
}

/* single-pass scan with decoupled lookback; also computes dis and cur */
__global__ void k_scan() {
    int t = threadIdx.x, b = blockIdx.x;
    int i = b*256 + t;
    unsigned long long pk = (i < N_NODES) ? g_deg64[i] : 0ULL;
    int v = (int)(pk >> 52);
    float deg = (float)((double)(pk & ((1ULL << 52) - 1ULL)) * (1.0 / DEG_SCALE));
    int lane = t & 31, wp = t >> 5;
    int x = v;
    #pragma unroll
    for (int o = 1; o < 32; o <<= 1) {
        int y = __shfl_up_sync(0xffffffffu, x, o);
        if (lane >= o) x += y;
    }
    __shared__ int wt[8];
    __shared__ int s_off;
    if (lane == 31) wt[wp] = x;
    if (t == 0) s_off = 0;
    __syncthreads();
    if (wp == 0 && lane < 8) {
        int y = wt[lane];
        #pragma unroll
        for (int o = 1; o < 8; o <<= 1) {
            int z = __shfl_up_sync(0xffu, y, o);
            if (lane >= o) y += z;
        }
        wt[lane] = y;
    }
    __syncthreads();
    int incl = x + (wp ? wt[wp-1] : 0);
    if (t == 0) {
        g_bsum[b] = wt[7];
        __threadfence();
        atomicExch(&g_flag[b], 1);
    }
    int part = 0;
    if (t < b) {
        while (atomicAdd(&g_flag[t], 0) == 0) { }
        part = g_bsum[t];
    }
    #pragma unroll
    for (int o = 16; o; o >>= 1) part += __shfl_xor_sync(0xffffffffu, part, o);
    if (lane == 0 && part != 0) atomicAdd(&s_off, part);
    __syncthreads();
    if (i < N_NODES) {
        int p = incl - v + s_off;
        g_rowptr[i] = p;
        g_cur[i] = p;
        g_dis[i] = (deg > 0.f) ? rsqrtf(fmaxf(deg, 1e-30f)) : 0.f;
    }
    if (b == NB_SCAN-1 && t == 255) g_rowptr[N_NODES] = N_EDGES;
}

__global__ void k_fill(const int* __restrict__ src, const int* __restrict__ dst,
                       const float* __restrict__ ew) {
    int e = blockIdx.x*blockDim.x + threadIdx.x;
    if (e < N_EDGES) {
        int s = src[e], d = dst[e];
        int p = atomicAdd(&g_cur[d], 1);
        g_colw[p] = make_int2(s, __float_as_int(g_dis[s] * ew[e] * g_dis[d]));
    }
}

/* ---------------- propagation ------------------------------------------ */
/* fused 3-pass fp16 F=4 prop chain: x16->pa16->pb16->pc16, grid barriers */
__global__ void __launch_bounds__(256, 6)
k_prop4h3() {
    int gt = blockIdx.x*blockDim.x + threadIdx.x;
    int n = gt >> 2, j = gt & 3;
    const uint32_t* bufs_in[3]  = {g_x16,  g_pa16, g_pb16};
    uint32_t*       bufs_out[3] = {g_pa16, g_pb16, g_pc16};
    int s = 0, e = 0;
    if (n < N_NODES) { s = g_rowptr[n]; e = g_rowptr[n+1]; }
    #pragma unroll 1
    for (int pass = 0; pass < 3; pass++) {
        const uint32_t* in = bufs_in[pass];
        uint32_t* out = bufs_out[pass];
        if (n < N_NODES) {
            float4 acc = make_float4(0.f,0.f,0.f,0.f);
            for (int i = s; i < e; i += 4) {
                int2  m[4];
                uint2 v[4];
                #pragma unroll
                for (int k = 0; k < 4; k++) {
                    int idx = i + k;
                    m[k] = (idx < e) ? __ldg(&g_colw[idx]) : make_int2(0, 0);
                }
                #pragma unroll
                for (int k = 0; k < 4; k++)
                    v[k] = __ldg((const uint2*)(in + m[k].x*8 + j*2));
                #pragma unroll
                for (int k = 0; k < 4; k++) {
                    float w = __int_as_float(m[k].y);
                    float2 f;
                    f = __half22float2(u2h(v[k].x)); acc.x += w*f.x; acc.y += w*f.y;
                    f = __half22float2(u2h(v[k].y)); acc.z += w*f.x; acc.w += w*f.y;
                }
            }
            uint2 pk;
            pk.x = h2u(__floats2half2_rn(acc.x, acc.y));
            pk.y = h2u(__floats2half2_rn(acc.z, acc.w));
            *(uint2*)(out + n*8 + j*2) = pk;
        }
        if (pass < 2) gridbar(&g_gbar[pass], GR4);
    }
}

/* fused layer-3 Horner chain + output epilogue + state zeroing */
__global__ void __launch_bounds__(256, 6)
k_prop2_all(const float* __restrict__ b3,
            const float* __restrict__ mask,
            const float* __restrict__ mean_y,
            const float* __restrict__ std_y,
            const float* __restrict__ vmin, const float* __restrict__ vmax,
            const float* __restrict__ qmin, const float* __restrict__ qmax,
            float* __restrict__ out) {
    int gt = blockIdx.x*blockDim.x + threadIdx.x;
    int n = gt >> 2, j = gt & 3;
    int s = 0, e = 0;
    if (n < N_NODES) { s = g_rowptr[n]; e = g_rowptr[n+1]; }
    /* pass layout: (in, add, out): (sa, sb, pc), (pc, pa, sa2=sb reused? no) */
    const float* ins[3]  = {g_sa, g_pc, g_sb};
    const float* adds[2] = {g_sb, g_pa};
    float*       outs[2] = {g_pc, g_sb};
    #pragma unroll 1
    for (int pass = 0; pass < 3; pass++) {
        const float* in = ins[pass];
        float2 acc = make_float2(0.f, 0.f);
        if (n < N_NODES) {
            for (int i = s; i < e; i += 4) {
                int2   m[4];
                float2 v[4];
                #pragma unroll
                for (int k = 0; k < 4; k++) {
                    int idx = i + k;
                    m[k] = (idx < e) ? __ldg(&g_colw[idx]) : make_int2(0, 0);
                }
                #pragma unroll
                for (int k = 0; k < 4; k++)
                    v[k] = __ldg((const float2*)(in + (size_t)(m[k].x*4 + j)*2));
                #pragma unroll
                for (int k = 0; k < 4; k++) {
                    float w = __int_as_float(m[k].y);
                    acc.x += w*v[k].x; acc.y += w*v[k].y;
                }
            }
        }
        if (pass < 2) {
            if (n < N_NODES) {
                float2 d = *(const float2*)(adds[pass] + (size_t)(n*4 + j)*2);
                acc.x += d.x; acc.y += d.y;
                *(float2*)(outs[pass] + (size_t)(n*4 + j)*2) = acc;
            }
            gridbar(&g_gbar[2 + pass], GR4);
        } else {
            /* re-zero accumulation state for the next graph replay */
            if (gt < N_NODES) g_deg64[gt] = 0ULL;
            if (gt < 256) g_flag[gt] = 0;
            if (gt < 8) g_gbar[gt] = 0;
            if (n < N_NODES) {
                float2 z = *(const float2*)(g_pb + (size_t)(n*4 + j)*2);
                float u0 = acc.x + z.x + __ldg(&b3[0]);
                float u1 = acc.y + z.y + __ldg(&b3[1]);
                float s0 = std_y[n*2], s1 = std_y[n*2+1];
                if (isinf(s0)) s0 = 0.f;
                if (isinf(s1)) s1 = 0.f;
                float o0 = (u0*s0 + mean_y[n*2])   * mask[n*2];
                float o1 = (u1*s1 + mean_y[n*2+1]) * mask[n*2+1];
                o0 = fminf(fmaxf(o0, vmin[n]), vmax[n]);
                o1 = fminf(fmaxf(o1, qmin[n]), qmax[n]);
                *(float2*)&out[(size_t)(j*N_NODES + n)*2] = make_float2(o0, o1);
            }
        }
    }
}

/* fp16 payload prop: warp per node, 4-way predicated edge loop */
__global__ void k_prop64h(const uint32_t* __restrict__ in, uint32_t* __restrict__ out) {
    int gt = blockIdx.x*blockDim.x + threadIdx.x;
    int n = gt >> 5, lane = gt & 31;
    if (n >= N_NODES) return;
    int s = g_rowptr[n], e = g_rowptr[n+1];
    float2 a0 = make_float2(0.f,0.f), a1 = a0, a2 = a0, a3 = a0;
    for (int i = s; i < e; i += 4) {
        int2  m[4];
        uint4 v[4];
        #pragma unroll
        for (int j = 0; j < 4; j++) {
            int idx = i + j;
            m[j] = (idx < e) ? __ldg(&g_colw[idx]) : make_int2(0, 0);
        }
        #pragma unroll
        for (int j = 0; j < 4; j++)
            v[j] = __ldg((const uint4*)(in + m[j].x*128 + lane*4));
        #pragma unroll
        for (int j = 0; j < 4; j++) {
            float w = __int_as_float(m[j].y);
            float2 f;
            f = __half22float2(u2h(v[j].x)); a0.x += w*f.x; a0.y += w*f.y;
            f = __half22float2(u2h(v[j].y)); a1.x += w*f.x; a1.y += w*f.y;
            f = __half22float2(u2h(v[j].z)); a2.x += w*f.x; a2.y += w*f.y;
            f = __half22float2(u2h(v[j].w)); a3.x += w*f.x; a3.y += w*f.y;
        }
    }
    uint4 o;
    o.x = h2u(__floats2half2_rn(a0.x, a0.y));
    o.y = h2u(__floats2half2_rn(a1.x, a1.y));
    o.z = h2u(__floats2half2_rn(a2.x, a2.y));
    o.w = h2u(__floats2half2_rn(a3.x, a3.y));
    *(uint4*)(out + n*128 + lane*4) = o;
}

/* ---------------- layer-1 GEMM (fp16 A direct) + BN + LReLU -> fp16 h --- */
__global__ void __launch_bounds__(256, 2)
k_gemm1_mma(const uint32_t* __restrict__ A0, const uint32_t* __restrict__ A1,
            const uint32_t* __restrict__ A2, const uint32_t* __restrict__ A3,
            const uint32_t* __restrict__ w1h, const uint32_t* __restrict__ w1l,
            const float* __restrict__ b1,
            const float* __restrict__ g1, const float* __restrict__ be1,
            uint32_t* __restrict__ hout) {
    extern __shared__ uint32_t smu[];
    float* smf = (float*)smu;
    const int t = threadIdx.x;
    const int lane = t & 31, wid = t >> 5;
    const int wrow = wid >> 1, wcol = wid & 1;
    const int r0 = blockIdx.x * 128;

    {
        int n = t >> 2, c4 = t & 3;
        int regbit = (c4 >> 1) & 1, q0 = (c4 & 1) * 2;
        int g = n & 7, nt = n >> 3;
        int b_w = 1024 + nt*64 + (g*4 + q0)*2 + regbit;
        uint2 vh = *(const uint2*)(w1h + n*8 + c4*2);
        uint2 vl = *(const uint2*)(w1l + n*8 + c4*2);
        smu[b_w]       = vh.x;
        smu[b_w + 2]   = vh.y;
        smu[512 + b_w]     = vl.x;
        smu[512 + b_w + 2] = vl.y;
    }
    #pragma unroll
    for (int sidx = 0; sidx < 2; sidx++) {
        int idx = sidx*256 + t;
        int row = idx >> 2, c4 = idx & 3;
        int rr = row & 15, mt = row >> 4;
        int regbit = (c4 >> 1) & 1, q0 = (c4 & 1) * 2;
        int g = rr & 7, abit = rr >> 3;
        int a_w = mt*128 + (g*4 + q0)*4 + abit + 2*regbit;
        const uint32_t* Ap = (c4 == 0) ? A0 : (c4 == 1) ? A1 : (c4 == 2) ? A2 : A3;
        uint2 v = *(const uint2*)(Ap + (size_t)(r0 + row)*2);
        smu[a_w]     = v.x;
        smu[a_w + 4] = v.y;
    }
    __syncthreads();

    float c[2][4][4];
    #pragma unroll
    for (int m = 0; m < 2; m++)
        #pragma unroll
        for (int n = 0; n < 4; n++)
            #pragma unroll
            for (int k = 0; k < 4; k++) c[m][n][k] = 0.f;

    {
        uint4 ah[2];
        #pragma unroll
        for (int mt = 0; mt < 2; mt++) {
            int mtile = wrow*2 + mt;
            ah[mt] = *(const uint4*)(smu + mtile*128 + lane*4);
        }
        uint2 bh[4], bl[4];
        #pragma unroll
        for (int nt = 0; nt < 4; nt++) {
            int ntile = wcol*4 + nt;
            bh[nt] = *(const uint2*)(smu + 1024 + ntile*64 + lane*2);
            bl[nt] = *(const uint2*)(smu + 1536 + ntile*64 + lane*2);
        }
        #pragma unroll
        for (int mt = 0; mt < 2; mt++)
            #pragma unroll
            for (int nt = 0; nt < 4; nt++) {
                MMAH(c[mt][nt], ah[mt].x, ah[mt].y, ah[mt].z, ah[mt].w,
                     bh[nt].x, bh[nt].y);
                MMAH(c[mt][nt], ah[mt].x, ah[mt].y, ah[mt].z, ah[mt].w,
                     bl[nt].x, bl[nt].y);
            }
    }
    __syncthreads();

    {
        float* so = smf;
        const int g = lane >> 2, q = lane & 3;
        #pragma unroll
        for (int mt = 0; mt < 2; mt++) {
            int lr = wrow*32 + mt*16 + g;
            #pragma unroll
            for (int nt = 0; nt < 4; nt++) {
                int col = wcol*32 + nt*8 + 2*q;
                float bx = __ldg(&b1[col]), by = __ldg(&b1[col+1]);
                so[lr*68+col]       = c[mt][nt][0] + bx;
                so[lr*68+col+1]     = c[mt][nt][1] + by;
                so[(lr+8)*68+col]   = c[mt][nt][2] + bx;
                so[(lr+8)*68+col+1] = c[mt][nt][3] + by;
            }
        }
    }
    __syncthreads();
    {
        const float* so = smf;
        int sub = lane >> 3, c8 = (lane & 7) * 8;
        #pragma unroll
        for (int nn = 0; nn < 4; nn++) {
            int node = wid*4 + nn;
            int gnode = blockIdx.x*32 + node;
            int gn = gnode < N_NODES ? gnode : N_NODES-1;
            const float* rp = so + (node*4 + sub)*68 + c8;
            float4 v0 = *(const float4*)rp;
            float4 v1 = *(const float4*)(rp + 4);
            float s = v0.x+v0.y+v0.z+v0.w + v1.x+v1.y+v1.z+v1.w;
            float q = v0.x*v0.x+v0.y*v0.y+v0.z*v0.z+v0.w*v0.w
                    + v1.x*v1.x+v1.y*v1.y+v1.z*v1.z+v1.w*v1.w;
            #pragma unroll
            for (int o = 16; o; o >>= 1) {
                s += __shfl_xor_sync(0xffffffffu, s, o);
                q += __shfl_xor_sync(0xffffffffu, q, o);
            }
            float mu  = s * (1.f/256.f);
            float var = q * (1.f/256.f) - mu*mu;
            float sc  = __ldg(&g1[gn]) * rsqrtf(var + BN_EPS);
            float bb  = __ldg(&be1[gn]);
            float o0, o1, o2, o3, o4, o5, o6, o7, f;
            f = sc*(v0.x-mu)+bb; o0 = f > 0.f ? f : SLOPE*f;
            f = sc*(v0.y-mu)+bb; o1 = f > 0.f ? f : SLOPE*f;
            f = sc*(v0.z-mu)+bb; o2 = f > 0.f ? f : SLOPE*f;
            f = sc*(v0.w-mu)+bb; o3 = f > 0.f ? f : SLOPE*f;
            f = sc*(v1.x-mu)+bb; o4 = f > 0.f ? f : SLOPE*f;
            f = sc*(v1.y-mu)+bb; o5 = f > 0.f ? f : SLOPE*f;
            f = sc*(v1.z-mu)+bb; o6 = f > 0.f ? f : SLOPE*f;
            f = sc*(v1.w-mu)+bb; o7 = f > 0.f ? f : SLOPE*f;
            if (gnode < N_NODES) {
                uint4 pk;
                pk.x = h2u(__floats2half2_rn(o0, o1));
                pk.y = h2u(__floats2half2_rn(o2, o3));
                pk.z = h2u(__floats2half2_rn(o4, o5));
                pk.w = h2u(__floats2half2_rn(o6, o7));
                *(uint4*)&hout[(size_t)(r0 + node*4 + sub)*32 + (lane & 7)*4] = pk;
            }
        }
    }
}

/* ---------------- layer-2 GEMM (fp16 A, fp16 B) + BN + projections ------ */
#define STG_U32 3072
#define SW3_OFF 8704
__global__ void __launch_bounds__(256, 2)
k_gemm2_mma(const uint32_t* __restrict__ A0, const uint32_t* __restrict__ A1,
            const uint32_t* __restrict__ A2, const uint32_t* __restrict__ A3,
            const uint32_t* __restrict__ wph,
            const float* __restrict__ b2,
            const float* __restrict__ g2, const float* __restrict__ be2,
            const float* __restrict__ W3,
            float* __restrict__ p0, float* __restrict__ p1,
            float* __restrict__ p2, float* __restrict__ p3) {
    extern __shared__ uint32_t smu[];
    float* smf = (float*)smu;
    const int t = threadIdx.x;
    const int lane = t & 31, wid = t >> 5;
    const int wrow = wid >> 1, wcol = wid & 1;
    const int r0 = blockIdx.x * 128;

    #pragma unroll
    for (int i2 = t; i2 < 512; i2 += 256) {
        int kch = i2 >> 6, f = i2 & 63;
        smf[SW3_OFF + i2] = W3[(kch >> 1)*128 + f*2 + (kch & 1)];
    }

    int a_w[4], a_src[4];
    #pragma unroll
    for (int i = 0; i < 4; i++) {
        int idx = i*256 + t;
        int row = idx >> 3, c4 = idx & 7;
        int rr = row & 15, mt = row >> 4;
        int ks = c4 >> 2, regbit = (c4 >> 1) & 1, q0 = (c4 & 1) * 2;
        int g = rr & 7, abit = rr >> 3;
        a_w[i] = (mt*2 + ks)*128 + (g*4 + q0)*4 + abit + 2*regbit;
        a_src[i] = row*32 + c4*2;
    }
    int b_w[2], b_src[2];
    #pragma unroll
    for (int i = 0; i < 2; i++) {
        int idx = i*256 + t;
        int n = idx >> 3, c4 = idx & 7;
        int ks = c4 >> 2, regbit = (c4 >> 1) & 1, q0 = (c4 & 1) * 2;
        int g = n & 7, nt = n >> 3;
        b_w[i] = 2048 + (nt*2 + ks)*64 + (g*4 + q0)*2 + regbit;
        b_src[i] = n*128 + c4*2;
    }

    float c[2][4][4];
    #pragma unroll
    for (int m = 0; m < 2; m++)
        #pragma unroll
        for (int n = 0; n < 4; n++)
            #pragma unroll
            for (int k = 0; k < 4; k++) c[m][n][k] = 0.f;

    uint2 pa[4], pbh[2];

    {
        #pragma unroll
        for (int i = 0; i < 4; i++)
            pa[i] = *(const uint2*)(A0 + (size_t)r0*32 + a_src[i]);
        #pragma unroll
        for (int i = 0; i < 2; i++)
            pbh[i] = *(const uint2*)(wph + b_src[i]);
        uint32_t* base = smu;
        #pragma unroll
        for (int i = 0; i < 4; i++) {
            base[a_w[i]]     = pa[i].x;
            base[a_w[i] + 4] = pa[i].y;
        }
        #pragma unroll
        for (int i = 0; i < 2; i++) {
            base[b_w[i]]     = pbh[i].x;
            base[b_w[i] + 2] = pbh[i].y;
        }
    }
    __syncthreads();

    #pragma unroll 1
    for (int cc = 0; cc < 8; cc++) {
        int stage = cc & 1;
        if (cc < 7) {
            int cn = cc + 1;
            const uint32_t* Ap = (cn < 2) ? A0 : (cn < 4) ? A1 : (cn < 6) ? A2 : A3;
            int kb = (cn & 1) * 16;
            #pragma unroll
            for (int i = 0; i < 4; i++)
                pa[i] = *(const uint2*)(Ap + (size_t)r0*32 + a_src[i] + kb);
            #pragma unroll
            for (int i = 0; i < 2; i++)
                pbh[i] = *(const uint2*)(wph + b_src[i] + cn*16);
        }
        {
            const uint32_t* base = smu + stage*STG_U32;
            #pragma unroll
            for (int ks = 0; ks < 2; ks++) {
                uint4 ah[2];
                #pragma unroll
                for (int mt = 0; mt < 2; mt++) {
                    int mtile = wrow*2 + mt;
                    ah[mt] = *(const uint4*)(base + (mtile*2+ks)*128 + lane*4);
                }
                uint2 bh[4];
                #pragma unroll
                for (int nt = 0; nt < 4; nt++) {
                    int ntile = wcol*4 + nt;
                    bh[nt] = *(const uint2*)(base + 2048 + (ntile*2+ks)*64 + lane*2);
                }
                #pragma unroll
                for (int mt = 0; mt < 2; mt++)
                    #pragma unroll
                    for (int nt = 0; nt < 4; nt++)
                        MMAH(c[mt][nt], ah[mt].x, ah[mt].y, ah[mt].z, ah[mt].w,
                             bh[nt].x, bh[nt].y);
            }
        }
        if (cc < 7) {
            uint32_t* base = smu + ((cc+1)&1)*STG_U32;
            #pragma unroll
            for (int i = 0; i < 4; i++) {
                base[a_w[i]]     = pa[i].x;
                base[a_w[i] + 4] = pa[i].y;
            }
            #pragma unroll
            for (int i = 0; i < 2; i++) {
                base[b_w[i]]     = pbh[i].x;
                base[b_w[i] + 2] = pbh[i].y;
            }
        }
        __syncthreads();
    }

    /* ---- fused BN2 + LeakyReLU + W3 projections ---- */
    {
        float* so = smf;
        const int g = lane >> 2, q = lane & 3;
        #pragma unroll
        for (int mt = 0; mt < 2; mt++) {
            int lr = wrow*32 + mt*16 + g;
            #pragma unroll
            for (int nt = 0; nt < 4; nt++) {
                int col = wcol*32 + nt*8 + 2*q;
                float bx = __ldg(&b2[col]), by = __ldg(&b2[col+1]);
                so[lr*68+col]       = c[mt][nt][0] + bx;
                so[lr*68+col+1]     = c[mt][nt][1] + by;
                so[(lr+8)*68+col]   = c[mt][nt][2] + bx;
                so[(lr+8)*68+col+1] = c[mt][nt][3] + by;
            }
        }
    }
    __syncthreads();
    {
        const float* so = smf;
        const float* sw3 = smf + SW3_OFF;
        int sub = lane >> 3, c8 = (lane & 7) * 8;
        #pragma unroll
        for (int nn = 0; nn < 4; nn++) {
            int node = wid*4 + nn;
            int gnode = blockIdx.x*32 + node;
            int gn = gnode < N_NODES ? gnode : N_NODES-1;
            const float* rp = so + (node*4 + sub)*68 + c8;
            float4 v0 = *(const float4*)rp;
            float4 v1 = *(const float4*)(rp + 4);
            float s = v0.x+v0.y+v0.z+v0.w + v1.x+v1.y+v1.z+v1.w;
            float q = v0.x*v0.x+v0.y*v0.y+v0.z*v0.z+v0.w*v0.w
                    + v1.x*v1.x+v1.y*v1.y+v1.z*v1.z+v1.w*v1.w;
            #pragma unroll
            for (int o = 16; o; o >>= 1) {
                s += __shfl_xor_sync(0xffffffffu, s, o);
                q += __shfl_xor_sync(0xffffffffu, q, o);
            }
            float mu  = s * (1.f/256.f);
            float var = q * (1.f/256.f) - mu*mu;
            float sc  = __ldg(&g2[gn]) * rsqrtf(var + BN_EPS);
            float bb  = __ldg(&be2[gn]);
            float o0, o1, o2, o3, o4, o5, o6, o7, f;
            f = sc*(v0.x-mu)+bb; o0 = f > 0.f ? f : SLOPE*f;
            f = sc*(v0.y-mu)+bb; o1 = f > 0.f ? f : SLOPE*f;
            f = sc*(v0.z-mu)+bb; o2 = f > 0.f ? f : SLOPE*f;
            f = sc*(v0.w-mu)+bb; o3 = f > 0.f ? f : SLOPE*f;
            f = sc*(v1.x-mu)+bb; o4 = f > 0.f ? f : SLOPE*f;
            f = sc*(v1.y-mu)+bb; o5 = f > 0.f ? f : SLOPE*f;
            f = sc*(v1.z-mu)+bb; o6 = f > 0.f ? f : SLOPE*f;
            f = sc*(v1.w-mu)+bb; o7 = f > 0.f ? f : SLOPE*f;
            float pr[8];
            #pragma unroll
            for (int kch = 0; kch < 8; kch++) {
                const float* w = sw3 + kch*64 + c8;
                float4 w0 = *(const float4*)w;
                float4 w1 = *(const float4*)(w + 4);
                pr[kch] = o0*w0.x + o1*w0.y + o2*w0.z + o3*w0.w
                        + o4*w1.x + o5*w1.y + o6*w1.z + o7*w1.w;
            }
            #pragma unroll
            for (int m = 1; m <= 4; m <<= 1) {
                #pragma unroll
                for (int kch = 0; kch < 8; kch++)
                    pr[kch] += __shfl_xor_sync(0xffffffffu, pr[kch], m);
            }
            if ((lane & 7) == 0 && gnode < N_NODES) {
                size_t grow = (size_t)(r0 + node*4 + sub)*2;
                *(float2*)&p0[grow] = make_float2(pr[0], pr[1]);
                *(float2*)&p1[grow] = make_float2(pr[2], pr[3]);
                *(float2*)&p2[grow] = make_float2(pr[4], pr[5]);
                *(float2*)&p3[grow] = make_float2(pr[6], pr[7]);
            }
        }
    }
}

/* ======================================================================= */
extern "C" void kernel_launch(void* const* d_in, const int* in_sizes, int n_in,
                              void* d_out, int out_size) {
    const float* x      = (const float*)d_in[0];
    const int*   src    = (const int*)  d_in[1];
    const int*   dst    = (const int*)  d_in[2];
    const float* ew     = (const float*)d_in[3];
    const float* W1     = (const float*)d_in[4];
    const float* b1     = (const float*)d_in[5];
    const float* W2     = (const float*)d_in[6];
    const float* b2     = (const float*)d_in[7];
    const float* W3     = (const float*)d_in[8];
    const float* b3     = (const float*)d_in[9];
    const float* g1     = (const float*)d_in[10];
    const float* be1    = (const float*)d_in[11];
    const float* g2     = (const float*)d_in[12];
    const float* be2    = (const float*)d_in[13];
    const float* mask   = (const float*)d_in[14];
    const float* mean_y = (const float*)d_in[15];
    const float* std_y  = (const float*)d_in[16];
    const float* vmin   = (const float*)d_in[17];
    const float* vmax   = (const float*)d_in[18];
    const float* qmin   = (const float*)d_in[19];
    const float* qmax   = (const float*)d_in[20];
    float* out = (float*)d_out;

    float *pa, *pb, *sa;
    uint32_t *x16, *pa16, *pb16, *pc16;
    uint32_t *h16, *t116, *t216, *t316, *w2ph, *w1ph, *w1pl;
    float *sb;
    cudaGetSymbolAddress((void**)&pa,  g_pa);
    cudaGetSymbolAddress((void**)&pb,  g_pb);
    cudaGetSymbolAddress((void**)&sa,  g_sa);
    cudaGetSymbolAddress((void**)&sb,  g_sb);
    cudaGetSymbolAddress((void**)&x16,  g_x16);
    cudaGetSymbolAddress((void**)&pa16, g_pa16);
    cudaGetSymbolAddress((void**)&pb16, g_pb16);
    cudaGetSymbolAddress((void**)&pc16, g_pc16);
    cudaGetSymbolAddress((void**)&h16,  g_h16);
    cudaGetSymbolAddress((void**)&t116, g_t116);
    cudaGetSymbolAddress((void**)&t216, g_t216);
    cudaGetSymbolAddress((void**)&t316, g_t316);
    cudaGetSymbolAddress((void**)&w2ph, g_w2p_hi);
    cudaGetSymbolAddress((void**)&w1ph, g_w1p_hi);
    cudaGetSymbolAddress((void**)&w1pl, g_w1p_lo);
    float *pc;
    cudaGetSymbolAddress((void**)&pc,  g_pc);

    static int smem_set = 0;
    if (!smem_set) {
        cudaFuncSetAttribute(k_gemm2_mma, cudaFuncAttributeMaxDynamicSharedMemorySize, 36864);
        cudaFuncSetAttribute(k_gemm1_mma, cudaFuncAttributeMaxDynamicSharedMemorySize, 34816);
        smem_set = 1;
    }

    const int TB = 256;
    int gE  = (N_EDGES + TB - 1) / TB;
    int gW  = (N_NODES*32 + TB - 1) / TB;

    /* preprocessing: deg64/flags/gbar zeroed by previous call's tail */
    k_deg_w2<<<gE, TB>>>(dst, ew, x, W2, W1);
    k_scan  <<<NB_SCAN, 256>>>();
    k_fill  <<<gE, TB>>>(src, dst, ew);

    /* layer 1: fused 3-pass fp16 prop chain, then GEMM+BN+LReLU -> fp16 h */
    k_prop4h3<<<GR4, TB>>>();
    k_gemm1_mma<<<RPAD/128, 256, 34816>>>(x16, pa16, pb16, pc16, w1ph, w1pl,
                                          b1, g1, be1, h16);

    /* layer 2: 3x fp16 prop64, fused GEMM+BN+projections -> p0..p3 */
    k_prop64h<<<gW, TB>>>(h16,  t116);
    k_prop64h<<<gW, TB>>>(t116, t216);
    k_prop64h<<<gW, TB>>>(t216, t316);
    k_gemm2_mma<<<RPAD/128, 256, 36864>>>(h16, t116, t216, t316, w2ph,
                                          b2, g2, be2, W3, pb, pa, sb, sa);

    /* layer 3: fused Horner chain + epilogue (p0=pb, p1=pa, p2=sb, p3=sa) */
    k_prop2_all<<<GR4, TB>>>(b3, mask, mean_y, std_y,
                             vmin, vmax, qmin, qmax, out);
}